// round 7
// baseline (speedup 1.0000x reference)
#include <cuda_runtime.h>
#include <cuda_bf16.h>
#include <cstdint>

#define N_USER 100000
#define N_ITEM 50000
#define N_TOTAL (N_USER + N_ITEM)   // 150000
#define D 64
#define NNZ 4000000
#define B 2048
#define NEG (4 * B)                  // 8192
#define NSLOTS (B + B + NEG)         // 12288
#define NWORDS ((N_TOTAL + 31) / 32) // 4688 words = 18.75 KB bitset

#define NBLK 592                     // 148 SMs x 4 blocks — all co-resident
#define NTHR 256
#define WPB (NTHR / 32)              // 8 warps per block
#define NWARPS (NBLK * WPB)          // 4736
#define EPT 4
#define EPB (NTHR * EPT)             // 1024 edges per chunk
#define NCHUNKS ((NNZ + EPB - 1) / EPB)  // 3907
#define MAX_HITS 192                 // mean hits/chunk ~80, sd ~9 -> huge margin

// Device scratch (zero-init at load). Phase C returns g_flags to all-zero each
// call; g_acc rows are re-zeroed in Phase A before use; g_bar is a monotone
// ticket counter that never needs reset (modular-safe comparisons).
__device__ float    g_acc[(size_t)N_TOTAL * D];   // 38.4 MB
__device__ unsigned g_flags[NWORDS];              // L1-hot bitset
__device__ unsigned g_bar;                        // grid barrier tickets

// slot -> global row id in [0, N_TOTAL)
__device__ __forceinline__ int slot_row(int s, const int* __restrict__ users,
                                        const int* __restrict__ pos,
                                        const int* __restrict__ neg) {
    if (s < B) return users[s];
    if (s < 2 * B) return N_USER + pos[s - B];
    return N_USER + neg[s - 2 * B];
}

// Ticket grid barrier: valid for any number of calls across graph replays as
// long as all NBLK blocks are co-resident (guaranteed by launch shape).
__device__ __forceinline__ void grid_barrier() {
    __syncthreads();
    if (threadIdx.x == 0) {
        __threadfence();                                  // release
        unsigned ticket = atomicAdd(&g_bar, 1u);
        unsigned target = ticket / NBLK * NBLK + NBLK;
        while ((int)(*(volatile unsigned*)&g_bar - target) < 0) { }
    }
    __syncthreads();
    __threadfence();                                      // acquire
}

__global__ void __launch_bounds__(NTHR, 4)
k_fused(const int* __restrict__ users,
        const int* __restrict__ pos,
        const int* __restrict__ neg,
        const float* __restrict__ user_emb,
        const float* __restrict__ item_emb,
        const int* __restrict__ adj_row,
        const int* __restrict__ adj_col,
        const float* __restrict__ adj_val,
        float* __restrict__ out) {
    __shared__ int  s_cnt;
    __shared__ int2 s_hits[MAX_HITS];                     // (edge index, row)

    const int tid   = threadIdx.x;
    const int lane  = tid & 31;
    const int wid   = tid >> 5;
    const int gwarp = blockIdx.x * WPB + wid;

    // ================= Phase A: mark flags + zero needed acc rows ==========
    for (int s = gwarp; s < NSLOTS; s += NWARPS) {
        int r = slot_row(s, users, pos, neg);             // broadcast load
        if (lane == 0) atomicOr(&g_flags[r >> 5], 1u << (r & 31));
        float2 z; z.x = 0.0f; z.y = 0.0f;
        reinterpret_cast<float2*>(g_acc + (size_t)r * D)[lane] = z;
    }

    grid_barrier();

    // ================= Phase B: staged filtered SpMM ========================
    const int half = lane >> 4;
    const int l4   = lane & 15;

    for (int chunk = blockIdx.x; chunk < NCHUNKS; chunk += NBLK) {
        if (tid == 0) s_cnt = 0;
        __syncthreads();

        int base = chunk * EPB + tid * EPT;
        if (base < NNZ) {                                 // NNZ%4==0 -> full int4
            int4 r4 = __ldg(reinterpret_cast<const int4*>(adj_row) + (base >> 2));
            int rr[EPT] = {r4.x, r4.y, r4.z, r4.w};
#pragma unroll
            for (int k = 0; k < EPT; k++) {
                int r = rr[k];
                if ((__ldg(&g_flags[r >> 5]) >> (r & 31)) & 1u) {
                    int idx = atomicAdd(&s_cnt, 1);
                    if (idx < MAX_HITS) s_hits[idx] = make_int2(base + k, r);
                }
            }
        }
        __syncthreads();

        int n = s_cnt < MAX_HITS ? s_cnt : MAX_HITS;
        for (int h = wid * 2 + half; h < n; h += 2 * WPB) {
            int2 hit = s_hits[h];                         // LDS broadcast per half
            int   i  = hit.x;
            int   r  = hit.y;
            int   c  = __ldg(adj_col + i);
            float v  = __ldg(adj_val + i);
            const float* src = (c < N_USER)
                                   ? (user_emb + (size_t)c * D)
                                   : (item_emb + (size_t)(c - N_USER) * D);
            float4 e = __ldg(reinterpret_cast<const float4*>(src) + l4);
            float* dst = g_acc + (size_t)r * D + l4 * 4;
            asm volatile("red.global.add.v4.f32 [%0], {%1, %2, %3, %4};"
                         :: "l"(dst),
                            "f"(v * e.x), "f"(v * e.y),
                            "f"(v * e.z), "f"(v * e.w)
                         : "memory");
        }
        __syncthreads();
    }

    grid_barrier();

    // ================= Phase C: gather outputs + reset flags ================
    for (int s = gwarp; s < NSLOTS; s += NWARPS) {
        int r = slot_row(s, users, pos, neg);
        if (lane == 0) g_flags[r >> 5] = 0u;              // racing zeros — benign

        const float* e0 = (r < N_USER) ? (user_emb + (size_t)r * D)
                                       : (item_emb + (size_t)(r - N_USER) * D);
        float2 e = __ldg(reinterpret_cast<const float2*>(e0) + lane);
        // g_acc was updated via L2 atomics; bypass L1 (this block's Phase-A
        // zero-stores could have left a stale line).
        float2 a = __ldcg(reinterpret_cast<const float2*>(g_acc + (size_t)r * D)
                          + lane);
        float2 o;
        o.x = (e.x + 3.0f * a.x) * 0.25f;
        o.y = (e.y + 3.0f * a.y) * 0.25f;
        reinterpret_cast<float2*>(out)[(size_t)s * (D / 2) + lane] = o;
    }
}

// ---------------------------------------------------------------------------
// launch: single persistent kernel
// ---------------------------------------------------------------------------
extern "C" void kernel_launch(void* const* d_in, const int* in_sizes, int n_in,
                              void* d_out, int out_size) {
    const int*   users    = (const int*)d_in[0];
    const int*   pos      = (const int*)d_in[1];
    const int*   neg      = (const int*)d_in[2];
    // d_in[3] mask, d_in[4] norm_adj: unused placeholders
    const float* user_emb = (const float*)d_in[5];
    const float* item_emb = (const float*)d_in[6];
    const int*   adj_row  = (const int*)d_in[7];
    const int*   adj_col  = (const int*)d_in[8];
    const float* adj_val  = (const float*)d_in[9];
    float* out = (float*)d_out;

    (void)in_sizes; (void)n_in; (void)out_size;

    k_fused<<<NBLK, NTHR>>>(users, pos, neg, user_emb, item_emb,
                            adj_row, adj_col, adj_val, out);
}

// round 8
// speedup vs baseline: 1.1371x; 1.1371x over previous
#include <cuda_runtime.h>
#include <cuda_bf16.h>
#include <cstdint>

#define N_USER 100000
#define N_ITEM 50000
#define N_TOTAL (N_USER + N_ITEM)   // 150000
#define D 64
#define NNZ 4000000
#define B 2048
#define NEG (4 * B)                  // 8192
#define NSLOTS (B + B + NEG)         // 12288
#define NWORDS ((N_TOTAL + 31) / 32) // 4688 words = 18.75 KB bitset

#define NBLK 1184                    // 148 SMs x 8 blocks — all co-resident
#define NTHR 256
#define WPB (NTHR / 32)              // 8 warps per block
#define NWARPS (NBLK * WPB)          // 9472
#define EPT 4
#define EPB (NTHR * EPT)             // 1024 edges per chunk
#define NCHUNKS ((NNZ + EPB - 1) / EPB)  // 3907
#define MAX_HITS 192                 // mean hits/chunk ~80, sd ~9 -> huge margin

// Device scratch (zero-init at load). Phase C returns g_flags to all-zero each
// call; g_acc rows are re-zeroed in Phase A before use; g_bar is a monotone
// ticket counter that never needs reset (modular-safe comparisons).
__device__ float    g_acc[(size_t)N_TOTAL * D];   // 38.4 MB
__device__ unsigned g_flags[NWORDS];              // L1-hot bitset
__device__ unsigned g_bar;                        // grid barrier tickets

// slot -> global row id in [0, N_TOTAL)
__device__ __forceinline__ int slot_row(int s, const int* __restrict__ users,
                                        const int* __restrict__ pos,
                                        const int* __restrict__ neg) {
    if (s < B) return users[s];
    if (s < 2 * B) return N_USER + pos[s - B];
    return N_USER + neg[s - 2 * B];
}

// Ticket grid barrier: valid across any number of graph replays as long as
// all NBLK blocks are co-resident (guaranteed by launch shape + reg cap).
__device__ __forceinline__ void grid_barrier() {
    __syncthreads();
    if (threadIdx.x == 0) {
        __threadfence();                                  // release
        unsigned ticket = atomicAdd(&g_bar, 1u);
        unsigned target = ticket / NBLK * NBLK + NBLK;
        while ((int)(*(volatile unsigned*)&g_bar - target) < 0) { }
    }
    __syncthreads();
    __threadfence();                                      // acquire
}

__global__ void __launch_bounds__(NTHR, 8)
k_fused(const int* __restrict__ users,
        const int* __restrict__ pos,
        const int* __restrict__ neg,
        const float* __restrict__ user_emb,
        const float* __restrict__ item_emb,
        const int* __restrict__ adj_row,
        const int* __restrict__ adj_col,
        const float* __restrict__ adj_val,
        float* __restrict__ out) {
    __shared__ int  s_cnt;
    __shared__ int2 s_hits[MAX_HITS];                     // (edge index, row)

    const int tid   = threadIdx.x;
    const int lane  = tid & 31;
    const int wid   = tid >> 5;
    const int gwarp = blockIdx.x * WPB + wid;

    // ================= Phase A: mark flags + zero needed acc rows ==========
    for (int s = gwarp; s < NSLOTS; s += NWARPS) {
        int r = slot_row(s, users, pos, neg);             // broadcast load
        if (lane == 0) atomicOr(&g_flags[r >> 5], 1u << (r & 31));
        float2 z; z.x = 0.0f; z.y = 0.0f;
        reinterpret_cast<float2*>(g_acc + (size_t)r * D)[lane] = z;
    }

    grid_barrier();

    // ================= Phase B: staged filtered SpMM ========================
    const int half = lane >> 4;
    const int l4   = lane & 15;

    for (int chunk = blockIdx.x; chunk < NCHUNKS; chunk += NBLK) {
        if (tid == 0) s_cnt = 0;
        __syncthreads();

        int base = chunk * EPB + tid * EPT;
        if (base < NNZ) {                                 // NNZ%4==0 -> full int4
            int4 r4 = __ldg(reinterpret_cast<const int4*>(adj_row) + (base >> 2));
            int rr[EPT] = {r4.x, r4.y, r4.z, r4.w};
#pragma unroll
            for (int k = 0; k < EPT; k++) {
                int r = rr[k];
                if ((__ldg(&g_flags[r >> 5]) >> (r & 31)) & 1u) {
                    int idx = atomicAdd(&s_cnt, 1);
                    if (idx < MAX_HITS) s_hits[idx] = make_int2(base + k, r);
                }
            }
        }
        __syncthreads();

        int n = s_cnt < MAX_HITS ? s_cnt : MAX_HITS;
        for (int h = wid * 2 + half; h < n; h += 2 * WPB) {
            int2 hit = s_hits[h];                         // LDS broadcast per half
            int   i  = hit.x;
            int   r  = hit.y;
            int   c  = __ldg(adj_col + i);
            float v  = __ldg(adj_val + i);
            const float* src = (c < N_USER)
                                   ? (user_emb + (size_t)c * D)
                                   : (item_emb + (size_t)(c - N_USER) * D);
            float4 e = __ldg(reinterpret_cast<const float4*>(src) + l4);
            float* dst = g_acc + (size_t)r * D + l4 * 4;
            asm volatile("red.global.add.v4.f32 [%0], {%1, %2, %3, %4};"
                         :: "l"(dst),
                            "f"(v * e.x), "f"(v * e.y),
                            "f"(v * e.z), "f"(v * e.w)
                         : "memory");
        }
        __syncthreads();
    }

    grid_barrier();

    // ================= Phase C: gather outputs + reset flags ================
    for (int s = gwarp; s < NSLOTS; s += NWARPS) {
        int r = slot_row(s, users, pos, neg);
        if (lane == 0) g_flags[r >> 5] = 0u;              // racing zeros — benign

        const float* e0 = (r < N_USER) ? (user_emb + (size_t)r * D)
                                       : (item_emb + (size_t)(r - N_USER) * D);
        float2 e = __ldg(reinterpret_cast<const float2*>(e0) + lane);
        // g_acc was updated via L2 atomics; bypass L1 (this block's Phase-A
        // zero-stores could have left a stale line).
        float2 a = __ldcg(reinterpret_cast<const float2*>(g_acc + (size_t)r * D)
                          + lane);
        float2 o;
        o.x = (e.x + 3.0f * a.x) * 0.25f;
        o.y = (e.y + 3.0f * a.y) * 0.25f;
        reinterpret_cast<float2*>(out)[(size_t)s * (D / 2) + lane] = o;
    }
}

// ---------------------------------------------------------------------------
// launch: single persistent kernel
// ---------------------------------------------------------------------------
extern "C" void kernel_launch(void* const* d_in, const int* in_sizes, int n_in,
                              void* d_out, int out_size) {
    const int*   users    = (const int*)d_in[0];
    const int*   pos      = (const int*)d_in[1];
    const int*   neg      = (const int*)d_in[2];
    // d_in[3] mask, d_in[4] norm_adj: unused placeholders
    const float* user_emb = (const float*)d_in[5];
    const float* item_emb = (const float*)d_in[6];
    const int*   adj_row  = (const int*)d_in[7];
    const int*   adj_col  = (const int*)d_in[8];
    const float* adj_val  = (const float*)d_in[9];
    float* out = (float*)d_out;

    (void)in_sizes; (void)n_in; (void)out_size;

    k_fused<<<NBLK, NTHR>>>(users, pos, neg, user_emb, item_emb,
                            adj_row, adj_col, adj_val, out);
}

// round 9
// speedup vs baseline: 1.3416x; 1.1798x over previous
#include <cuda_runtime.h>
#include <cuda_bf16.h>
#include <cstdint>

#define N_USER 100000
#define N_ITEM 50000
#define N_TOTAL (N_USER + N_ITEM)   // 150000
#define D 64
#define NNZ 4000000
#define B 2048
#define NEG (4 * B)                  // 8192
#define NSLOTS (B + B + NEG)         // 12288
#define NWORDS ((N_TOTAL + 31) / 32) // 4688 words = 18.75 KB bitset

#define EPT 4
#define SCAN_THREADS 256
#define EPB (SCAN_THREADS * EPT)     // 1024 edges per block
#define MAX_HITS 192                 // mean ~80/chunk, sd ~8.6 -> 13 sigma margin

// Device scratch (zero-init at load).
// g_acc2: dense per-owner-slot accumulator (3 MB, L2-hot) — zeroed coalesced in K2.
// g_rowmap: row -> owner slot + 1. Never reset: only freshly flagged rows probed.
// g_flags: needed-row bitset; K4 restores it to all-zero each call.
__device__ float    g_acc2[(size_t)NSLOTS * D];   // 3 MB
__device__ int      g_rowmap[N_TOTAL];            // 600 KB
__device__ unsigned g_flags[NWORDS];              // 18.75 KB

// slot -> global row id in [0, N_TOTAL)
__device__ __forceinline__ int slot_row(int s, const int* __restrict__ users,
                                        const int* __restrict__ pos,
                                        const int* __restrict__ neg) {
    if (s < B) return users[s];
    if (s < 2 * B) return N_USER + pos[s - B];
    return N_USER + neg[s - 2 * B];
}

// ---------------------------------------------------------------------------
// K2: coalesced-zero the dense accumulator + claim rows + set flags.
// ---------------------------------------------------------------------------
__global__ void k_prep(const int* __restrict__ users,
                       const int* __restrict__ pos,
                       const int* __restrict__ neg) {
    int gtid = blockIdx.x * blockDim.x + threadIdx.x;
    int nthr = gridDim.x * blockDim.x;
    // dense, coalesced zero of 3 MB
    float4 z = make_float4(0.f, 0.f, 0.f, 0.f);
    for (int i = gtid; i < NSLOTS * D / 4; i += nthr)
        reinterpret_cast<float4*>(g_acc2)[i] = z;
    // claim + flag (racing word stores: any single winner is fine)
    if (gtid < NSLOTS) {
        int r = slot_row(gtid, users, pos, neg);
        g_rowmap[r] = gtid + 1;
        atomicOr(&g_flags[r >> 5], 1u << (r & 31));
    }
}

// ---------------------------------------------------------------------------
// K3: staged filtered SpMM. Scan stages (col, valbits, owner) per hit; drain
// is half-warp per hit: LDS -> float4 gather -> red.v4 into the 3MB hot acc.
// ---------------------------------------------------------------------------
__global__ void k_spmm(const int* __restrict__ adj_row,
                       const int* __restrict__ adj_col,
                       const float* __restrict__ adj_val,
                       const float* __restrict__ user_emb,
                       const float* __restrict__ item_emb) {
    __shared__ int  s_cnt;
    __shared__ int4 s_hits[MAX_HITS];               // (col, val bits, owner, -)

    int tid = threadIdx.x;
    if (tid == 0) s_cnt = 0;
    __syncthreads();

    // ---- scan: 4 edges per thread; streaming row loads (no L2 pollution) ----
    int base = (blockIdx.x * SCAN_THREADS + tid) * EPT;
    if (base < NNZ) {                                // NNZ % 4 == 0 -> full int4
        int4 r4 = __ldcs(reinterpret_cast<const int4*>(adj_row) + (base >> 2));
        int rr[EPT] = {r4.x, r4.y, r4.z, r4.w};
#pragma unroll
        for (int k = 0; k < EPT; k++) {
            int r = rr[k];
            if ((__ldg(&g_flags[r >> 5]) >> (r & 31)) & 1u) {
                int   c     = __ldcs(adj_col + base + k);
                float v     = __ldcs(adj_val + base + k);
                int   owner = g_rowmap[r] - 1;
                int idx = atomicAdd(&s_cnt, 1);
                if (idx < MAX_HITS)
                    s_hits[idx] = make_int4(c, __float_as_int(v), owner, 0);
            }
        }
    }
    __syncthreads();

    // ---- drain: half-warp per hit, two hits in flight ----
    int n = s_cnt < MAX_HITS ? s_cnt : MAX_HITS;
    int lane = tid & 31;
    int wid  = tid >> 5;
    int half = lane >> 4;
    int l4   = lane & 15;

    for (int h = wid * 2 + half; h < n; h += 32) {
        // hit A
        int4 ha = s_hits[h];
        const float* srcA = (ha.x < N_USER)
                                ? (user_emb + (size_t)ha.x * D)
                                : (item_emb + (size_t)(ha.x - N_USER) * D);
        float4 eA = __ldg(reinterpret_cast<const float4*>(srcA) + l4);
        // hit B (keep second gather in flight before first REDG)
        int h2 = h + 16;
        bool hasB = (h2 < n);
        int4 hb = hasB ? s_hits[h2] : make_int4(0, 0, 0, 0);
        float4 eB = make_float4(0.f, 0.f, 0.f, 0.f);
        const float* srcB = (hb.x < N_USER)
                                ? (user_emb + (size_t)hb.x * D)
                                : (item_emb + (size_t)(hb.x - N_USER) * D);
        if (hasB) eB = __ldg(reinterpret_cast<const float4*>(srcB) + l4);

        float vA = __int_as_float(ha.y);
        float* dstA = g_acc2 + (size_t)ha.z * D + l4 * 4;
        asm volatile("red.global.add.v4.f32 [%0], {%1, %2, %3, %4};"
                     :: "l"(dstA),
                        "f"(vA * eA.x), "f"(vA * eA.y),
                        "f"(vA * eA.z), "f"(vA * eA.w)
                     : "memory");
        if (hasB) {
            float vB = __int_as_float(hb.y);
            float* dstB = g_acc2 + (size_t)hb.z * D + l4 * 4;
            asm volatile("red.global.add.v4.f32 [%0], {%1, %2, %3, %4};"
                         :: "l"(dstB),
                            "f"(vB * eB.x), "f"(vB * eB.y),
                            "f"(vB * eB.z), "f"(vB * eB.w)
                         : "memory");
        }
    }
}

// ---------------------------------------------------------------------------
// K4: out[s] = (e0[row] + 3*acc2[owner]) / 4. Two slots per warp (float4);
// also resets the flag bitset. L1 is flushed at launch, so plain loads see
// the REDG results in L2.
// ---------------------------------------------------------------------------
__global__ void k_gather(const int* __restrict__ users,
                         const int* __restrict__ pos,
                         const int* __restrict__ neg,
                         const float* __restrict__ user_emb,
                         const float* __restrict__ item_emb,
                         float* __restrict__ out) {
    int gtid = blockIdx.x * blockDim.x + threadIdx.x;
    int warp = gtid >> 5;
    int lane = gtid & 31;
    int half = lane >> 4;
    int l4   = lane & 15;
    int s = warp * 2 + half;
    if (s >= NSLOTS) return;
    int r = slot_row(s, users, pos, neg);           // broadcast per half
    if (l4 == 0) g_flags[r >> 5] = 0u;              // racing zeros — benign
    int owner = g_rowmap[r] - 1;                    // broadcast per half

    const float* e0 = (r < N_USER) ? (user_emb + (size_t)r * D)
                                   : (item_emb + (size_t)(r - N_USER) * D);
    float4 e = __ldg(reinterpret_cast<const float4*>(e0) + l4);
    float4 a = *(reinterpret_cast<const float4*>(g_acc2 + (size_t)owner * D) + l4);
    float4 o;
    o.x = (e.x + 3.0f * a.x) * 0.25f;
    o.y = (e.y + 3.0f * a.y) * 0.25f;
    o.z = (e.z + 3.0f * a.z) * 0.25f;
    o.w = (e.w + 3.0f * a.w) * 0.25f;
    reinterpret_cast<float4*>(out)[(size_t)s * (D / 4) + l4] = o;
}

// ---------------------------------------------------------------------------
// launch
// ---------------------------------------------------------------------------
extern "C" void kernel_launch(void* const* d_in, const int* in_sizes, int n_in,
                              void* d_out, int out_size) {
    const int*   users    = (const int*)d_in[0];
    const int*   pos      = (const int*)d_in[1];
    const int*   neg      = (const int*)d_in[2];
    // d_in[3] mask, d_in[4] norm_adj: unused placeholders
    const float* user_emb = (const float*)d_in[5];
    const float* item_emb = (const float*)d_in[6];
    const int*   adj_row  = (const int*)d_in[7];
    const int*   adj_col  = (const int*)d_in[8];
    const float* adj_val  = (const float*)d_in[9];
    float* out = (float*)d_out;

    (void)in_sizes; (void)n_in; (void)out_size;

    {   // K2: zero dense acc + claim + flags
        int threads = 256, blocks = 512;            // 131072 threads
        k_prep<<<blocks, threads>>>(users, pos, neg);
    }
    {   // K3: staged filtered SpMM
        int blocks = (NNZ + EPB - 1) / EPB;         // 3907
        k_spmm<<<blocks, SCAN_THREADS>>>(adj_row, adj_col, adj_val,
                                         user_emb, item_emb);
    }
    {   // K4: gather + blend + flag reset (2 slots per warp)
        int warps = (NSLOTS + 1) / 2;               // 6144
        int threads = 256;
        int blocks = (warps * 32 + threads - 1) / threads;  // 768
        k_gather<<<blocks, threads>>>(users, pos, neg, user_emb, item_emb, out);
    }
}

// round 10
// speedup vs baseline: 1.3729x; 1.0234x over previous
#include <cuda_runtime.h>
#include <cuda_bf16.h>
#include <cstdint>

#define N_USER 100000
#define N_ITEM 50000
#define N_TOTAL (N_USER + N_ITEM)   // 150000
#define D 64
#define NNZ 4000000
#define B 2048
#define NEG (4 * B)                  // 8192
#define NSLOTS (B + B + NEG)         // 12288
#define NWORDS ((N_TOTAL + 31) / 32) // 4688 words = 18.75 KB bitset

#define EPT 4
#define SCAN_THREADS 256
#define EPB (SCAN_THREADS * EPT)     // 1024 edges per block
#define MAX_HITS 192                 // mean ~80/chunk, sd ~8.6 -> 13 sigma margin

// Device scratch (zero-init at load).
// g_acc2: dense per-owner-slot accumulator (3 MB, L2-hot), zeroed in K2.
// g_rowmap: row -> owner slot + 1. Never reset (only freshly flagged rows probed).
// g_flags: needed-row bitset; K4 restores all-zero each call.
__device__ float    g_acc2[(size_t)NSLOTS * D];   // 3 MB
__device__ int      g_rowmap[N_TOTAL];            // 600 KB
__device__ unsigned g_flags[NWORDS];              // 18.75 KB

// slot -> global row id in [0, N_TOTAL)
__device__ __forceinline__ int slot_row(int s, const int* __restrict__ users,
                                        const int* __restrict__ pos,
                                        const int* __restrict__ neg) {
    if (s < B) return users[s];
    if (s < 2 * B) return N_USER + pos[s - B];
    return N_USER + neg[s - 2 * B];
}

// ---------------------------------------------------------------------------
// K2: coalesced-zero dense accumulator + claim rows + set flags.
// ---------------------------------------------------------------------------
__global__ void k_prep(const int* __restrict__ users,
                       const int* __restrict__ pos,
                       const int* __restrict__ neg) {
    int gtid = blockIdx.x * blockDim.x + threadIdx.x;
    int nthr = gridDim.x * blockDim.x;
    float4 z = make_float4(0.f, 0.f, 0.f, 0.f);
    for (int i = gtid; i < NSLOTS * D / 4; i += nthr)
        reinterpret_cast<float4*>(g_acc2)[i] = z;
    if (gtid < NSLOTS) {
        int r = slot_row(gtid, users, pos, neg);
        g_rowmap[r] = gtid + 1;                     // racing stores: any winner OK
        atomicOr(&g_flags[r >> 5], 1u << (r & 31));
    }
}

// ---------------------------------------------------------------------------
// K3 (PDL): prefetch edge data BEFORE the grid dependency sync, then probe
// flags, stage hits (col, val, owner) in smem, drain with float4 gather +
// red.v4 into the hot dense accumulator.
// ---------------------------------------------------------------------------
__global__ void __launch_bounds__(SCAN_THREADS)
k_spmm(const int* __restrict__ adj_row,
       const int* __restrict__ adj_col,
       const float* __restrict__ adj_val,
       const float* __restrict__ user_emb,
       const float* __restrict__ item_emb) {
    __shared__ int  s_cnt;
    __shared__ int4 s_hits[MAX_HITS];               // (col, val bits, owner, -)

    int tid = threadIdx.x;
    if (tid == 0) s_cnt = 0;

    // ---- dependency-free prefetch: full edge records, streaming ----
    int base = (blockIdx.x * SCAN_THREADS + tid) * EPT;
    int4 r4 = make_int4(0, 0, 0, 0);
    int4 c4 = make_int4(0, 0, 0, 0);
    float4 v4 = make_float4(0.f, 0.f, 0.f, 0.f);
    bool valid = (base < NNZ);                      // NNZ % 4 == 0 -> full int4
    if (valid) {
        r4 = __ldcs(reinterpret_cast<const int4*>(adj_row) + (base >> 2));
        c4 = __ldcs(reinterpret_cast<const int4*>(adj_col) + (base >> 2));
        v4 = __ldcs(reinterpret_cast<const float4*>(adj_val) + (base >> 2));
    }

    // Wait for K2 (flags / rowmap / zeroed acc) to be complete.
    cudaGridDependencySynchronize();
    __syncthreads();                                // s_cnt visible

    if (valid) {
        int   rr[EPT] = {r4.x, r4.y, r4.z, r4.w};
        int   cc[EPT] = {c4.x, c4.y, c4.z, c4.w};
        float vv[EPT] = {v4.x, v4.y, v4.z, v4.w};
#pragma unroll
        for (int k = 0; k < EPT; k++) {
            int r = rr[k];
            if ((__ldg(&g_flags[r >> 5]) >> (r & 31)) & 1u) {
                int owner = g_rowmap[r] - 1;
                int idx = atomicAdd(&s_cnt, 1);
                if (idx < MAX_HITS)
                    s_hits[idx] = make_int4(cc[k], __float_as_int(vv[k]), owner, 0);
            }
        }
    }
    __syncthreads();

    // ---- drain: half-warp per hit, two hits in flight ----
    int n = s_cnt < MAX_HITS ? s_cnt : MAX_HITS;
    int lane = tid & 31;
    int wid  = tid >> 5;
    int half = lane >> 4;
    int l4   = lane & 15;

    for (int h = wid * 2 + half; h < n; h += 32) {
        int4 ha = s_hits[h];
        const float* srcA = (ha.x < N_USER)
                                ? (user_emb + (size_t)ha.x * D)
                                : (item_emb + (size_t)(ha.x - N_USER) * D);
        float4 eA = __ldg(reinterpret_cast<const float4*>(srcA) + l4);

        int h2 = h + 16;
        bool hasB = (h2 < n);
        int4 hb = hasB ? s_hits[h2] : make_int4(0, 0, 0, 0);
        float4 eB = make_float4(0.f, 0.f, 0.f, 0.f);
        const float* srcB = (hb.x < N_USER)
                                ? (user_emb + (size_t)hb.x * D)
                                : (item_emb + (size_t)(hb.x - N_USER) * D);
        if (hasB) eB = __ldg(reinterpret_cast<const float4*>(srcB) + l4);

        float vA = __int_as_float(ha.y);
        float* dstA = g_acc2 + (size_t)ha.z * D + l4 * 4;
        asm volatile("red.global.add.v4.f32 [%0], {%1, %2, %3, %4};"
                     :: "l"(dstA),
                        "f"(vA * eA.x), "f"(vA * eA.y),
                        "f"(vA * eA.z), "f"(vA * eA.w)
                     : "memory");
        if (hasB) {
            float vB = __int_as_float(hb.y);
            float* dstB = g_acc2 + (size_t)hb.z * D + l4 * 4;
            asm volatile("red.global.add.v4.f32 [%0], {%1, %2, %3, %4};"
                         :: "l"(dstB),
                            "f"(vB * eB.x), "f"(vB * eB.y),
                            "f"(vB * eB.z), "f"(vB * eB.w)
                         : "memory");
        }
    }
}

// ---------------------------------------------------------------------------
// K4 (PDL): pre-sync loads of slot ids + e0 rows (inputs only), then sync,
// then acc2 read + blend + store + flag reset.
// ---------------------------------------------------------------------------
__global__ void k_gather(const int* __restrict__ users,
                         const int* __restrict__ pos,
                         const int* __restrict__ neg,
                         const float* __restrict__ user_emb,
                         const float* __restrict__ item_emb,
                         float* __restrict__ out) {
    int gtid = blockIdx.x * blockDim.x + threadIdx.x;
    int warp = gtid >> 5;
    int lane = gtid & 31;
    int half = lane >> 4;
    int l4   = lane & 15;
    int s = warp * 2 + half;

    int r = 0;
    float4 e = make_float4(0.f, 0.f, 0.f, 0.f);
    bool valid = (s < NSLOTS);
    if (valid) {
        r = slot_row(s, users, pos, neg);           // input-only: safe pre-sync
        const float* e0 = (r < N_USER) ? (user_emb + (size_t)r * D)
                                       : (item_emb + (size_t)(r - N_USER) * D);
        e = __ldg(reinterpret_cast<const float4*>(e0) + l4);
    }

    cudaGridDependencySynchronize();                // wait for K3's REDGs
    if (!valid) return;

    if (l4 == 0) g_flags[r >> 5] = 0u;              // racing zeros — benign
    int owner = g_rowmap[r] - 1;

    float4 a = *(reinterpret_cast<const float4*>(g_acc2 + (size_t)owner * D) + l4);
    float4 o;
    o.x = (e.x + 3.0f * a.x) * 0.25f;
    o.y = (e.y + 3.0f * a.y) * 0.25f;
    o.z = (e.z + 3.0f * a.z) * 0.25f;
    o.w = (e.w + 3.0f * a.w) * 0.25f;
    reinterpret_cast<float4*>(out)[(size_t)s * (D / 4) + l4] = o;
}

// ---------------------------------------------------------------------------
// launch: K2 normal; K3, K4 with programmatic dependent launch.
// ---------------------------------------------------------------------------
extern "C" void kernel_launch(void* const* d_in, const int* in_sizes, int n_in,
                              void* d_out, int out_size) {
    const int*   users    = (const int*)d_in[0];
    const int*   pos      = (const int*)d_in[1];
    const int*   neg      = (const int*)d_in[2];
    // d_in[3] mask, d_in[4] norm_adj: unused placeholders
    const float* user_emb = (const float*)d_in[5];
    const float* item_emb = (const float*)d_in[6];
    const int*   adj_row  = (const int*)d_in[7];
    const int*   adj_col  = (const int*)d_in[8];
    const float* adj_val  = (const float*)d_in[9];
    float* out = (float*)d_out;

    (void)in_sizes; (void)n_in; (void)out_size;

    // K2: normal launch
    k_prep<<<512, 256>>>(users, pos, neg);

    cudaLaunchAttribute attrs[1];
    attrs[0].id = cudaLaunchAttributeProgrammaticStreamSerialization;
    attrs[0].val.programmaticStreamSerializationAllowed = 1;

    // K3: PDL launch
    {
        cudaLaunchConfig_t cfg = {};
        cfg.gridDim  = dim3((NNZ + EPB - 1) / EPB);   // 3907
        cfg.blockDim = dim3(SCAN_THREADS);
        cfg.attrs = attrs;
        cfg.numAttrs = 1;
        cudaLaunchKernelEx(&cfg, k_spmm, adj_row, adj_col, adj_val,
                           user_emb, item_emb);
    }
    // K4: PDL launch
    {
        int warps = (NSLOTS + 1) / 2;                 // 6144
        cudaLaunchConfig_t cfg = {};
        cfg.gridDim  = dim3((warps * 32 + 255) / 256);  // 768
        cfg.blockDim = dim3(256);
        cfg.attrs = attrs;
        cfg.numAttrs = 1;
        cudaLaunchKernelEx(&cfg, k_gather, users, pos, neg,
                           user_emb, item_emb, out);
    }
}